// round 4
// baseline (speedup 1.0000x reference)
#include <cuda_runtime.h>
#include <cuda_bf16.h>
#include <cstdint>

#define BB 8
#define NN 1024
#define HH 8
#define DD 64
#define CC (HH*DD)   // 512

// Scratch
__device__ float g_Wh[BB*NN*CC];
__device__ float g_hp[BB*NN*CC];
__device__ float g_es  [BB*HH*NN];
__device__ float g_es01[BB*HH*NN];
__device__ float g_et  [BB*HH*NN];
__device__ float g_et01[BB*HH*NN];
__device__ float g_rZ  [BB*HH*NN];
__device__ float g_was [HH*64];   // [h][k]
__device__ float g_wat [HH*64];   // [h][k]

__device__ __forceinline__ uint32_t smem_u32(const void* p) {
    uint32_t a;
    asm("{ .reg .u64 t; cvta.to.shared.u64 t, %1; cvt.u32.u64 %0, t; }" : "=r"(a) : "l"(p));
    return a;
}

#define LDSM_T4(r0, r1, r2, r3, addr) \
    asm volatile("ldmatrix.sync.aligned.m8n8.x4.trans.shared.b16 {%0,%1,%2,%3}, [%4];" \
                 : "=r"(r0), "=r"(r1), "=r"(r2), "=r"(r3) : "r"(addr))

#define MMA16816(d0,d1,d2,d3, a0,a1,a2,a3, b0,b1) \
    asm volatile("mma.sync.aligned.m16n8k16.row.col.f32.bf16.bf16.f32 " \
                 "{%0,%1,%2,%3}, {%4,%5,%6,%7}, {%8,%9}, {%0,%1,%2,%3};" \
                 : "+f"(d0), "+f"(d1), "+f"(d2), "+f"(d3) \
                 : "r"(a0), "r"(a1), "r"(a2), "r"(a3), "r"(b0), "r"(b1))

__device__ __forceinline__ uint32_t pack_bf16(float a, float b) {
    __nv_bfloat162 t = __floats2bfloat162_rn(a, b);
    return *(uint32_t*)&t;
}
__device__ __forceinline__ uint32_t split_pair(float e0, float e1, uint32_t& lo) {
    float h0 = __bfloat162float(__float2bfloat16_rn(e0));
    float h1 = __bfloat162float(__float2bfloat16_rn(e1));
    lo = pack_bf16(e0 - h0, e1 - h1);
    return pack_bf16(h0, h1);
}

// ---------------------------------------------------------------------------
// K0: wa[h][k] = sum_d W[k, h*64+d] * a[d]   (s uses a[0:64], t uses a[64:128])
// grid 2 x 256 threads
// ---------------------------------------------------------------------------
__global__ __launch_bounds__(256) void k0_wa(const float* __restrict__ W,
                                             const float* __restrict__ a) {
    __shared__ float as[128];
    int tid = threadIdx.x;
    if (tid < 128) as[tid] = a[tid];
    __syncthreads();
    int g = blockIdx.x * 256 + tid;        // 0..511
    int k = g >> 3, hh = g & 7;
    const float4* w4 = (const float4*)(W + k * CC + hh * DD);
    float s = 0.f, t = 0.f;
#pragma unroll
    for (int q = 0; q < 16; q++) {
        float4 v = w4[q];
        s = fmaf(v.x, as[q*4+0], s); s = fmaf(v.y, as[q*4+1], s);
        s = fmaf(v.z, as[q*4+2], s); s = fmaf(v.w, as[q*4+3], s);
        t = fmaf(v.x, as[64+q*4+0], t); t = fmaf(v.y, as[64+q*4+1], t);
        t = fmaf(v.z, as[64+q*4+2], t); t = fmaf(v.w, as[64+q*4+3], t);
    }
    g_was[hh * 64 + k] = s;
    g_wat[hh * 64 + k] = t;
}

// ---------------------------------------------------------------------------
// K2: s[b,n,h] = h[b,n,:] . wa_s[h,:]  (and t);  exps stored.
// 256 blocks x 256 threads; block = 32 node-rows x 8 heads.
// ---------------------------------------------------------------------------
__global__ __launch_bounds__(256) void k2_vec(const float* __restrict__ hin) {
    __shared__ __align__(16) float hrow[32][68];
    __shared__ __align__(16) float was[8][64];
    __shared__ __align__(16) float wat[8][64];
    int tid = threadIdx.x;
    int n0 = blockIdx.x * 32;              // global row base (b*N+n)
    for (int idx = tid; idx < 2048; idx += 256) {
        int r = idx >> 6, k = idx & 63;
        hrow[r][k] = hin[(size_t)(n0 + r) * 64 + k];
    }
    for (int idx = tid; idx < 512; idx += 256) {
        was[idx >> 6][idx & 63] = g_was[idx];
        wat[idx >> 6][idx & 63] = g_wat[idx];
    }
    __syncthreads();
    int r = tid >> 3, hh = tid & 7;
    const float4* hv4 = (const float4*)hrow[r];
    const float4* ws4 = (const float4*)was[hh];
    const float4* wt4 = (const float4*)wat[hh];
    float s = 0.f, t = 0.f;
#pragma unroll
    for (int q = 0; q < 16; q++) {
        float4 hv = hv4[q], wv = ws4[q], tv = wt4[q];
        s = fmaf(hv.x, wv.x, s); s = fmaf(hv.y, wv.y, s);
        s = fmaf(hv.z, wv.z, s); s = fmaf(hv.w, wv.w, s);
        t = fmaf(hv.x, tv.x, t); t = fmaf(hv.y, tv.y, t);
        t = fmaf(hv.z, tv.z, t); t = fmaf(hv.w, tv.w, t);
    }
    int gr = n0 + r;
    int b = gr >> 10, n = gr & (NN - 1);
    int o = (b * HH + hh) * NN + n;
    g_es[o]   = __expf(s);        g_es01[o] = __expf(0.01f * s);
    g_et[o]   = __expf(t);        g_et01[o] = __expf(0.01f * t);
}

// ---------------------------------------------------------------------------
// K1: Wh = h @ W      [8192 x 64] @ [64 x 512], vectorized smem
// ---------------------------------------------------------------------------
__global__ __launch_bounds__(256) void k1_wh(const float* __restrict__ h,
                                             const float* __restrict__ W) {
    __shared__ __align__(16) float As[64][68];   // [row][k]
    __shared__ __align__(16) float Bs[64][68];   // [k][col]
    int tid = threadIdx.x;
    int r0 = blockIdx.y * 64;
    int c0 = blockIdx.x * 64;
    for (int idx = tid; idx < 4096; idx += 256) {
        int r = idx >> 6, k = idx & 63;
        As[r][k] = h[(size_t)(r0 + r) * 64 + k];
        Bs[r][k] = W[(size_t)r * CC + c0 + k];   // r = k-dim, k = col
    }
    __syncthreads();
    int tx = tid & 15, ty = tid >> 4;
    float acc[4][4] = {};
#pragma unroll
    for (int k4 = 0; k4 < 16; k4++) {
        float4 a4[4], b4[4];
#pragma unroll
        for (int r = 0; r < 4; r++) a4[r] = *(const float4*)&As[ty*4+r][k4*4];
#pragma unroll
        for (int kk = 0; kk < 4; kk++) b4[kk] = *(const float4*)&Bs[k4*4+kk][tx*4];
#pragma unroll
        for (int kk = 0; kk < 4; kk++) {
            float ak[4] = { kk==0?a4[0].x:kk==1?a4[0].y:kk==2?a4[0].z:a4[0].w,
                            kk==0?a4[1].x:kk==1?a4[1].y:kk==2?a4[1].z:a4[1].w,
                            kk==0?a4[2].x:kk==1?a4[2].y:kk==2?a4[2].z:a4[2].w,
                            kk==0?a4[3].x:kk==1?a4[3].y:kk==2?a4[3].z:a4[3].w };
            float bk[4] = { b4[kk].x, b4[kk].y, b4[kk].z, b4[kk].w };
#pragma unroll
            for (int r = 0; r < 4; r++)
#pragma unroll
                for (int c = 0; c < 4; c++)
                    acc[r][c] = fmaf(ak[r], bk[c], acc[r][c]);
        }
    }
#pragma unroll
    for (int r = 0; r < 4; r++)
#pragma unroll
        for (int c = 0; c < 4; c++)
            g_Wh[(size_t)(r0 + ty*4 + r) * CC + c0 + tx*4 + c] = acc[r][c];
}

// ---------------------------------------------------------------------------
// K3: Z[b,h,j] = sum_i max(es_i*et_j, es01_i*et01_j); store 1/Z
// ---------------------------------------------------------------------------
__global__ __launch_bounds__(256) void k3_z() {
    __shared__ __align__(16) float se[NN], se01[NN];
    int bh = blockIdx.x >> 2;
    int chunk = blockIdx.x & 3;
    int base = bh * NN;
    for (int i = threadIdx.x; i < NN; i += 256) {
        se[i]   = g_es[base + i];
        se01[i] = g_es01[base + i];
    }
    __syncthreads();
    int j = chunk * 256 + threadIdx.x;
    float etjv   = g_et[base + j];
    float et01jv = g_et01[base + j];
    const float4* se4   = (const float4*)se;
    const float4* se014 = (const float4*)se01;
    float a0 = 0.f, a1 = 0.f, a2 = 0.f, a3 = 0.f;
#pragma unroll 4
    for (int q = 0; q < 256; q++) {
        float4 e = se4[q], e1 = se014[q];
        a0 += fmaxf(e.x * etjv, e1.x * et01jv);
        a1 += fmaxf(e.y * etjv, e1.y * et01jv);
        a2 += fmaxf(e.z * etjv, e1.z * et01jv);
        a3 += fmaxf(e.w * etjv, e1.w * et01jv);
    }
    g_rZ[base + j] = 1.f / ((a0 + a1) + (a2 + a3));
}

// ---------------------------------------------------------------------------
// K4: tensor-core fused attention-apply, ping-pong double buffered.
// ---------------------------------------------------------------------------
__device__ __forceinline__ void k4_fill(int buf, int jt, int base, int bj, int bd,
                                        const float* whb,
                                        __nv_bfloat16 (*Vh)[32][72],
                                        __nv_bfloat16 (*Vl)[32][72],
                                        float (*etj)[32], float (*et01j)[32],
                                        int tid) {
    if (tid < 32) {
        etj[buf][tid]   = g_et  [base + jt + tid];
        et01j[buf][tid] = g_et01[base + jt + tid];
    }
    float rz = g_rZ[base + jt + bj];
    const float* src = whb + (size_t)(jt + bj) * CC + bd;
    float4 v0 = *(const float4*)(src);
    float4 v1 = *(const float4*)(src + 4);
    float f[8] = {v0.x*rz, v0.y*rz, v0.z*rz, v0.w*rz,
                  v1.x*rz, v1.y*rz, v1.z*rz, v1.w*rz};
    uint32_t lo0, lo1, lo2, lo3;
    uint32_t h0 = split_pair(f[0], f[1], lo0);
    uint32_t h1 = split_pair(f[2], f[3], lo1);
    uint32_t h2 = split_pair(f[4], f[5], lo2);
    uint32_t h3 = split_pair(f[6], f[7], lo3);
    uint4 ph = {h0, h1, h2, h3};
    uint4 pl = {lo0, lo1, lo2, lo3};
    *(uint4*)&Vh[buf][bj][bd] = ph;
    *(uint4*)&Vl[buf][bj][bd] = pl;
}

__global__ __launch_bounds__(256, 3) void k4_mma() {
    __shared__ __align__(16) __nv_bfloat16 Vh[2][32][72];
    __shared__ __align__(16) __nv_bfloat16 Vl[2][32][72];
    __shared__ float etj[2][32], et01j[2][32];

    int tid = threadIdx.x;
    int lane = tid & 31, w = tid >> 5;
    int bh = blockIdx.y;
    int b = bh >> 3, hh = bh & 7;
    int i0 = blockIdx.x * 128;
    int base = bh * NN;

    const float* whb = g_Wh + (size_t)(b * NN) * CC + hh * DD;

    int gr = lane >> 2;
    int ctg2 = (lane & 3) * 2;
    int r0 = i0 + w * 16 + gr;
    float es0    = g_es  [base + r0];
    float es01_0 = g_es01[base + r0];
    float es1    = g_es  [base + r0 + 8];
    float es01_1 = g_es01[base + r0 + 8];

    int bj = tid >> 3;
    int bd = (tid & 7) * 8;

    const uint32_t BS = 32 * 72 * 2;   // bytes per buffer
    uint32_t lmo = (uint32_t)(((lane & 15) * 72 + (lane >> 4) * 8) * 2);
    uint32_t vh_s = smem_u32(Vh) + lmo;
    uint32_t vl_s = smem_u32(Vl) + lmo;

    float acc[8][4] = {};

    k4_fill(0, 0, base, bj, bd, whb, Vh, Vl, etj, et01j, tid);
    __syncthreads();

    for (int chunk = 0; chunk < 32; chunk++) {
        int buf = chunk & 1;
        if (chunk + 1 < 32)
            k4_fill(buf ^ 1, (chunk + 1) * 32, base, bj, bd, whb, Vh, Vl, etj, et01j, tid);

        uint32_t vbo = (uint32_t)buf * BS;
#pragma unroll
        for (int c = 0; c < 2; c++) {
            int kb = c * 16 + ctg2;
            float et_0 = etj[buf][kb],     et01_0v = et01j[buf][kb];
            float et_1 = etj[buf][kb + 1], et01_1v = et01j[buf][kb + 1];
            float et_8 = etj[buf][kb + 8], et01_8v = et01j[buf][kb + 8];
            float et_9 = etj[buf][kb + 9], et01_9v = et01j[buf][kb + 9];

            uint32_t ah0, ah1, ah2, ah3, al0, al1, al2, al3;
            ah0 = split_pair(fmaxf(es0*et_0, es01_0*et01_0v),
                             fmaxf(es0*et_1, es01_0*et01_1v), al0);
            ah1 = split_pair(fmaxf(es1*et_0, es01_1*et01_0v),
                             fmaxf(es1*et_1, es01_1*et01_1v), al1);
            ah2 = split_pair(fmaxf(es0*et_8, es01_0*et01_8v),
                             fmaxf(es0*et_9, es01_0*et01_9v), al2);
            ah3 = split_pair(fmaxf(es1*et_8, es01_1*et01_8v),
                             fmaxf(es1*et_9, es01_1*et01_9v), al3);

            uint32_t coff = vbo + (uint32_t)(c * 16 * 72 * 2);
#pragma unroll
            for (int t = 0; t < 4; t++) {
                uint32_t bh0, bh1, bh2, bh3, bl0, bl1, bl2, bl3;
                LDSM_T4(bh0, bh1, bh2, bh3, vh_s + coff + t * 32);
                LDSM_T4(bl0, bl1, bl2, bl3, vl_s + coff + t * 32);
                MMA16816(acc[2*t][0], acc[2*t][1], acc[2*t][2], acc[2*t][3],
                         ah0, ah1, ah2, ah3, bh0, bh1);
                MMA16816(acc[2*t+1][0], acc[2*t+1][1], acc[2*t+1][2], acc[2*t+1][3],
                         ah0, ah1, ah2, ah3, bh2, bh3);
                MMA16816(acc[2*t][0], acc[2*t][1], acc[2*t][2], acc[2*t][3],
                         ah0, ah1, ah2, ah3, bl0, bl1);
                MMA16816(acc[2*t+1][0], acc[2*t+1][1], acc[2*t+1][2], acc[2*t+1][3],
                         ah0, ah1, ah2, ah3, bl2, bl3);
                MMA16816(acc[2*t][0], acc[2*t][1], acc[2*t][2], acc[2*t][3],
                         al0, al1, al2, al3, bh0, bh1);
                MMA16816(acc[2*t+1][0], acc[2*t+1][1], acc[2*t+1][2], acc[2*t+1][3],
                         al0, al1, al2, al3, bh2, bh3);
            }
        }
        __syncthreads();
    }

    float* dst0 = g_hp + (size_t)(b * NN + r0) * CC + hh * DD + ctg2;
    float* dst1 = dst0 + (size_t)8 * CC;
#pragma unroll
    for (int t = 0; t < 8; t++) {
        float2 o0 = {acc[t][0], acc[t][1]};
        float2 o1 = {acc[t][2], acc[t][3]};
        *(float2*)(dst0 + t * 8) = o0;
        *(float2*)(dst1 + t * 8) = o1;
    }
}

// ---------------------------------------------------------------------------
// K5: out = h_prime @ out_W + out_b    [8192 x 512] @ [512 x 64], vectorized
// ---------------------------------------------------------------------------
__global__ __launch_bounds__(256) void k5_out(const float* __restrict__ oW,
                                              const float* __restrict__ ob,
                                              float* __restrict__ out) {
    __shared__ __align__(16) float As[64][68];
    __shared__ __align__(16) float Bs[64][68];
    int tid = threadIdx.x;
    int r0 = blockIdx.x * 64;
    int tx = tid & 15, ty = tid >> 4;
    float acc[4][4] = {};
    for (int kt = 0; kt < CC; kt += 64) {
        __syncthreads();
        for (int idx = tid; idx < 4096; idx += 256) {
            int r = idx >> 6, k = idx & 63;
            As[r][k] = g_hp[(size_t)(r0 + r) * CC + kt + k];
            Bs[r][k] = oW[(size_t)(kt + r) * DD + k];
        }
        __syncthreads();
#pragma unroll
        for (int k4 = 0; k4 < 16; k4++) {
            float4 a4[4], b4[4];
#pragma unroll
            for (int r = 0; r < 4; r++) a4[r] = *(const float4*)&As[ty*4+r][k4*4];
#pragma unroll
            for (int kk = 0; kk < 4; kk++) b4[kk] = *(const float4*)&Bs[k4*4+kk][tx*4];
#pragma unroll
            for (int kk = 0; kk < 4; kk++) {
                float ak[4] = { kk==0?a4[0].x:kk==1?a4[0].y:kk==2?a4[0].z:a4[0].w,
                                kk==0?a4[1].x:kk==1?a4[1].y:kk==2?a4[1].z:a4[1].w,
                                kk==0?a4[2].x:kk==1?a4[2].y:kk==2?a4[2].z:a4[2].w,
                                kk==0?a4[3].x:kk==1?a4[3].y:kk==2?a4[3].z:a4[3].w };
                float bk[4] = { b4[kk].x, b4[kk].y, b4[kk].z, b4[kk].w };
#pragma unroll
                for (int r = 0; r < 4; r++)
#pragma unroll
                    for (int c = 0; c < 4; c++)
                        acc[r][c] = fmaf(ak[r], bk[c], acc[r][c]);
            }
        }
    }
#pragma unroll
    for (int r = 0; r < 4; r++)
#pragma unroll
        for (int c = 0; c < 4; c++)
            out[(size_t)(r0 + ty*4 + r) * DD + tx*4 + c] = acc[r][c] + ob[tx*4+c];
}

// ---------------------------------------------------------------------------
extern "C" void kernel_launch(void* const* d_in, const int* in_sizes, int n_in,
                              void* d_out, int out_size) {
    const float* h    = (const float*)d_in[0];
    const float* W    = (const float*)d_in[2];
    const float* a    = (const float*)d_in[3];
    const float* oW   = (const float*)d_in[4];
    const float* ob   = (const float*)d_in[5];
    float* out = (float*)d_out;

    k0_wa <<<2, 256>>>(W, a);
    k2_vec<<<(BB*NN)/32, 256>>>(h);
    k1_wh <<<dim3(CC/64, (BB*NN)/64), 256>>>(h, W);
    k3_z  <<<BB*HH*4, 256>>>();
    k4_mma<<<dim3(NN/128, BB*HH), 256>>>();
    k5_out<<<(BB*NN)/64, 256>>>(oW, ob, out);
}

// round 5
// speedup vs baseline: 1.1244x; 1.1244x over previous
#include <cuda_runtime.h>
#include <cstdint>
#include <cstddef>

#define BB 8
#define NN 1024
#define HH 8
#define DD 64
#define CC (HH*DD)   // 512

// Scratch
__device__ float g_Wh[BB*NN*CC];
__device__ float g_hp[BB*NN*CC];
__device__ float g_s   [BB*HH*NN];
__device__ float g_t   [BB*HH*NN];
__device__ float g_es  [BB*HH*NN];
__device__ float g_es01[BB*HH*NN];
__device__ float g_et  [BB*HH*NN];
__device__ float g_et01[BB*HH*NN];
__device__ float g_was [HH*64];
__device__ float g_wat [HH*64];

// ---------------------------------------------------------------------------
// K0: wa[h][k] = sum_d W[k, h*64+d] * a[d]
// ---------------------------------------------------------------------------
__global__ __launch_bounds__(256) void k0_wa(const float* __restrict__ W,
                                             const float* __restrict__ a) {
    __shared__ float as[128];
    int tid = threadIdx.x;
    if (tid < 128) as[tid] = a[tid];
    __syncthreads();
    int g = blockIdx.x * 256 + tid;
    int k = g >> 3, hh = g & 7;
    const float4* w4 = (const float4*)(W + k * CC + hh * DD);
    float s = 0.f, t = 0.f;
#pragma unroll
    for (int q = 0; q < 16; q++) {
        float4 v = w4[q];
        s = fmaf(v.x, as[q*4+0], s); s = fmaf(v.y, as[q*4+1], s);
        s = fmaf(v.z, as[q*4+2], s); s = fmaf(v.w, as[q*4+3], s);
        t = fmaf(v.x, as[64+q*4+0], t); t = fmaf(v.y, as[64+q*4+1], t);
        t = fmaf(v.z, as[64+q*4+2], t); t = fmaf(v.w, as[64+q*4+3], t);
    }
    g_was[hh * 64 + k] = s;
    g_wat[hh * 64 + k] = t;
}

// ---------------------------------------------------------------------------
// K2: s[b,n,h] = h[b,n,:].wa_s[h,:], t likewise; store s,t and 4 exps.
// ---------------------------------------------------------------------------
__global__ __launch_bounds__(256) void k2_vec(const float* __restrict__ hin) {
    __shared__ __align__(16) float hrow[32][68];
    __shared__ __align__(16) float was[8][64];
    __shared__ __align__(16) float wat[8][64];
    int tid = threadIdx.x;
    int n0 = blockIdx.x * 32;
    for (int idx = tid; idx < 2048; idx += 256) {
        int r = idx >> 6, k = idx & 63;
        hrow[r][k] = hin[(size_t)(n0 + r) * 64 + k];
    }
    for (int idx = tid; idx < 512; idx += 256) {
        was[idx >> 6][idx & 63] = g_was[idx];
        wat[idx >> 6][idx & 63] = g_wat[idx];
    }
    __syncthreads();
    int r = tid >> 3, hh = tid & 7;
    const float4* hv4 = (const float4*)hrow[r];
    const float4* ws4 = (const float4*)was[hh];
    const float4* wt4 = (const float4*)wat[hh];
    float s = 0.f, t = 0.f;
#pragma unroll
    for (int q = 0; q < 16; q++) {
        float4 hv = hv4[q], wv = ws4[q], tv = wt4[q];
        s = fmaf(hv.x, wv.x, s); s = fmaf(hv.y, wv.y, s);
        s = fmaf(hv.z, wv.z, s); s = fmaf(hv.w, wv.w, s);
        t = fmaf(hv.x, tv.x, t); t = fmaf(hv.y, tv.y, t);
        t = fmaf(hv.z, tv.z, t); t = fmaf(hv.w, tv.w, t);
    }
    int gr = n0 + r;
    int b = gr >> 10, n = gr & (NN - 1);
    int o = (b * HH + hh) * NN + n;
    g_s[o] = s;                   g_t[o] = t;
    g_es[o]   = __expf(s);        g_es01[o] = __expf(0.01f * s);
    g_et[o]   = __expf(t);        g_et01[o] = __expf(0.01f * t);
}

// ---------------------------------------------------------------------------
// K1: Wh = h @ W      [8192 x 64] @ [64 x 512]
// ---------------------------------------------------------------------------
__global__ __launch_bounds__(256) void k1_wh(const float* __restrict__ h,
                                             const float* __restrict__ W) {
    __shared__ __align__(16) float As[64][68];
    __shared__ __align__(16) float Bs[64][68];
    int tid = threadIdx.x;
    int r0 = blockIdx.y * 64;
    int c0 = blockIdx.x * 64;
    for (int idx = tid; idx < 4096; idx += 256) {
        int r = idx >> 6, k = idx & 63;
        As[r][k] = h[(size_t)(r0 + r) * 64 + k];
        Bs[r][k] = W[(size_t)r * CC + c0 + k];
    }
    __syncthreads();
    int tx = tid & 15, ty = tid >> 4;
    float acc[4][4] = {};
#pragma unroll
    for (int k4 = 0; k4 < 16; k4++) {
        float4 a4[4], b4[4];
#pragma unroll
        for (int r = 0; r < 4; r++) a4[r] = *(const float4*)&As[ty*4+r][k4*4];
#pragma unroll
        for (int kk = 0; kk < 4; kk++) b4[kk] = *(const float4*)&Bs[k4*4+kk][tx*4];
#pragma unroll
        for (int kk = 0; kk < 4; kk++) {
            float ak[4] = { kk==0?a4[0].x:kk==1?a4[0].y:kk==2?a4[0].z:a4[0].w,
                            kk==0?a4[1].x:kk==1?a4[1].y:kk==2?a4[1].z:a4[1].w,
                            kk==0?a4[2].x:kk==1?a4[2].y:kk==2?a4[2].z:a4[2].w,
                            kk==0?a4[3].x:kk==1?a4[3].y:kk==2?a4[3].z:a4[3].w };
            float bk[4] = { b4[kk].x, b4[kk].y, b4[kk].z, b4[kk].w };
#pragma unroll
            for (int r = 0; r < 4; r++)
#pragma unroll
                for (int c = 0; c < 4; c++)
                    acc[r][c] = fmaf(ak[r], bk[c], acc[r][c]);
        }
    }
#pragma unroll
    for (int r = 0; r < 4; r++)
#pragma unroll
        for (int c = 0; c < 4; c++)
            g_Wh[(size_t)(r0 + ty*4 + r) * CC + c0 + tx*4 + c] = acc[r][c];
}

// ---------------------------------------------------------------------------
// kF: fused sort/scan attention-apply, one block per (b,h).  O(N log N).
//   sort t asc (perm pi); wA[m]=et/Z, wB[m]=et01/Z at sorted pos m;
//   PreA/PreB = prefix sums of wX[m]*Wh[pi_m,:]; c_i = #{t <= -s_i};
//   h'_i = es_i*(TotA - PreA[c_i]) + es01_i*PreB[c_i].
//   Z_j from sorted-s scalar prefix sums of es/es01.
// ---------------------------------------------------------------------------
// smem layout (floats)
#define O_SV     0
#define O_PES    1024
#define O_PES01  2080
#define O_TV     3136
#define O_TPI    4160
#define O_WA     5184
#define O_WB     6208
#define O_ESS    7232
#define O_ES01S  8256
#define O_SORG   9280
#define O_CI     10304
#define O_QORD   11328
#define O_TOTA   12352
#define O_PART   12416
#define O_AUX    12672
#define O_AUX2   12928
#define O_BOFF   13184
#define O_CNT    13200
#define O_SIDX   13216
#define O_ETS    14272
#define O_ET01S  15296
#define O_LOCA   16384
#define O_LOCB   24576
#define O_WHC    32768
#define KF_FLOATS (32768 + 16384)
#define KF_SMEM_BYTES (KF_FLOATS * 4)

__device__ __forceinline__ int ub1024(const float* __restrict__ arr, float key) {
    int lo = 0, hi = 1024;
    while (lo < hi) {
        int mid = (lo + hi) >> 1;
        if (arr[mid] <= key) lo = mid + 1; else hi = mid;
    }
    return lo;   // count of elements <= key
}

__global__ __launch_bounds__(256) void kF_attn() {
    extern __shared__ float sm[];
    float* sv    = sm + O_SV;
    float* pes   = sm + O_PES;
    float* pes01 = sm + O_PES01;
    float* tv    = sm + O_TV;
    int*   tpi   = (int*)(sm + O_TPI);
    float* wA    = sm + O_WA;
    float* wB    = sm + O_WB;
    float* esS   = sm + O_ESS;
    float* es01S = sm + O_ES01S;
    float* sorg  = sm + O_SORG;
    int*   ci    = (int*)(sm + O_CI);
    int*   qord  = (int*)(sm + O_QORD);
    float* TotA  = sm + O_TOTA;
    float* part  = sm + O_PART;
    float* aux   = sm + O_AUX;
    float* aux2  = sm + O_AUX2;
    int*   boff  = (int*)(sm + O_BOFF);
    int*   cnt   = (int*)(sm + O_CNT);
    int*   sidx  = (int*)(sm + O_SIDX);
    float* etS   = sm + O_ETS;
    float* et01S = sm + O_ET01S;
    float* locA  = sm + O_LOCA;
    float* locB  = sm + O_LOCB;
    float* WhC   = sm + O_WHC;

    int tid = threadIdx.x;
    int bh = blockIdx.x;
    int b = bh >> 3, hh = bh & 7;
    int base = bh * NN;
    const float* __restrict__ wh = g_Wh;

    // ---- load ----
    for (int q = tid; q < 1024; q += 256) {
        float svv = g_s[base + q];
        sorg[q] = svv; sv[q] = svv; sidx[q] = q;
        float tvv = g_t[base + q];
        tv[q] = tvv; tpi[q] = q;
        esS[q]   = g_es  [base + q];
        es01S[q] = g_es01[base + q];
        etS[q]   = g_et  [base + q];
        et01S[q] = g_et01[base + q];
    }
    if (tid < 16) { boff[tid] = 0; cnt[tid] = 0; }
    __syncthreads();

    // ---- concurrent bitonic sorts: tid<128 sorts (sv,sidx), else (tv,tpi) ----
    {
        float* key; int* val; int t0;
        if (tid < 128) { key = sv; val = sidx; t0 = tid; }
        else           { key = tv; val = tpi;  t0 = tid - 128; }
        for (int k = 2; k <= 1024; k <<= 1) {
            for (int j = k >> 1; j > 0; j >>= 1) {
                __syncthreads();
                for (int i = t0; i < 1024; i += 128) {
                    int ixj = i ^ j;
                    if (ixj > i) {
                        bool up = ((i & k) == 0);
                        float a = key[i], bq = key[ixj];
                        if ((a > bq) == up) {
                            key[i] = bq; key[ixj] = a;
                            int tmp = val[i]; val[i] = val[ixj]; val[ixj] = tmp;
                        }
                    }
                }
            }
        }
    }
    __syncthreads();

    // ---- scalar prefix sums of es/es01 in s-sorted order ----
    {
        int m0 = tid * 4;
        int i0 = sidx[m0], i1 = sidx[m0+1], i2 = sidx[m0+2], i3 = sidx[m0+3];
        float x0 = esS[i0], x1 = esS[i1], x2 = esS[i2], x3 = esS[i3];
        float y0 = es01S[i0], y1 = es01S[i1], y2 = es01S[i2], y3 = es01S[i3];
        aux[tid]  = ((x0 + x1) + (x2 + x3));
        aux2[tid] = ((y0 + y1) + (y2 + y3));
        __syncthreads();
        for (int dd = 1; dd < 256; dd <<= 1) {
            float a = 0.f, a2 = 0.f;
            if (tid >= dd) { a = aux[tid - dd]; a2 = aux2[tid - dd]; }
            __syncthreads();
            aux[tid] += a; aux2[tid] += a2;
            __syncthreads();
        }
        float off  = (tid > 0) ? aux[tid - 1]  : 0.f;
        float off2 = (tid > 0) ? aux2[tid - 1] : 0.f;
        pes[m0]     = off;
        pes[m0 + 1] = off + x0;
        pes[m0 + 2] = off + x0 + x1;
        pes[m0 + 3] = off + x0 + x1 + x2;
        pes01[m0]     = off2;
        pes01[m0 + 1] = off2 + y0;
        pes01[m0 + 2] = off2 + y0 + y1;
        pes01[m0 + 3] = off2 + y0 + y1 + y2;
        if (tid == 255) {
            pes[1024]   = off  + (x0 + x1 + x2 + x3);
            pes01[1024] = off2 + (y0 + y1 + y2 + y3);
        }
    }
    __syncthreads();

    // ---- Z per sorted-t position -> wA, wB ----
    {
        float ES_tot   = pes[1024];
        float ES01_tot = pes01[1024];
        (void)ES01_tot;
        for (int m = tid; m < 1024; m += 256) {
            int cpr = ub1024(sv, -tv[m]);        // #{s_i <= -t_j}
            int jo = tpi[m];
            float et = etS[jo], et01 = et01S[jo];
            float Z = et * (ES_tot - pes[cpr]) + et01 * pes01[cpr];
            float rz = 1.f / Z;
            wA[m] = et * rz;
            wB[m] = et01 * rz;
        }
    }
    __syncthreads();

    // ---- TotA[d] = sum_m wA[m] * Wh[pi_m, d] ----
    {
        int g = tid >> 6, d = tid & 63;
        float p = 0.f;
        for (int m = g; m < 1024; m += 4) {
            size_t row = (size_t)(b * NN + tpi[m]) * CC + hh * DD + d;
            p = fmaf(wA[m], wh[row], p);
        }
        part[tid] = p;
        __syncthreads();
        if (tid < 64)
            TotA[tid] = (part[tid] + part[64 + tid]) + (part[128 + tid] + part[192 + tid]);
    }

    // ---- c_i and buckets ----
    for (int ii = tid; ii < 1024; ii += 256)
        ci[ii] = ub1024(tv, -sorg[ii]);          // #{t_j <= -s_i}
    __syncthreads();
    for (int ii = tid; ii < 1024; ii += 256) {
        int c = ci[ii];
        int bu = (c == 0) ? 0 : (1 + ((c - 1) >> 7));
        atomicAdd(&boff[bu + 1], 1);
    }
    __syncthreads();
    if (tid == 0)
        for (int q = 1; q <= 9; q++) boff[q] += boff[q - 1];
    __syncthreads();
    for (int ii = tid; ii < 1024; ii += 256) {
        int c = ci[ii];
        int bu = (c == 0) ? 0 : (1 + ((c - 1) >> 7));
        int pos = boff[bu] + atomicAdd(&cnt[bu], 1);
        qord[pos] = ii;
    }
    __syncthreads();

    // ---- bucket 0 (c=0): h' = es_i * TotA ----
    {
        int d = tid & 63;
        for (int q = boff[0] + (tid >> 6); q < boff[1]; q += 4) {
            int i = qord[q];
            g_hp[(size_t)(b * NN + i) * CC + hh * DD + d] = esS[i] * TotA[d];
        }
    }

    // ---- preload chunk 0 Wh rows (float4) ----
    {
        float4* dst = (float4*)WhC;
        const float4* src4 = (const float4*)wh;
        for (int q4 = tid; q4 < 2048; q4 += 256) {
            int row = q4 >> 4, dq = q4 & 15;
            dst[q4] = src4[(size_t)(b * NN + tpi[row]) * 128 + hh * 16 + dq];
        }
    }
    __syncthreads();

    // ---- 8 chunks: scan 128 sorted-j rows, prefetch next, serve queries ----
    float run = 0.f;
    for (int ch = 0; ch < 8; ch++) {
        int k0 = ch * 128, buf = ch & 1;
        if (tid < 128) {
            int half = tid >> 6, d = tid & 63;
            const float* w = half ? wB : wA;
            float* loc = half ? locB : locA;
            const float* src = WhC + buf * 8192;
#pragma unroll 8
            for (int m = 0; m < 128; m++) {
                run = fmaf(w[k0 + m], src[m * 64 + d], run);
                loc[m * 64 + d] = run;
            }
        } else if (ch < 7) {
            int t2 = tid - 128;
            int nk0 = k0 + 128;
            float4* dst = (float4*)(WhC + (buf ^ 1) * 8192);
            const float4* src4 = (const float4*)wh;
            for (int q4 = t2; q4 < 2048; q4 += 128) {
                int row = q4 >> 4, dq = q4 & 15;
                dst[q4] = src4[(size_t)(b * NN + tpi[nk0 + row]) * 128 + hh * 16 + dq];
            }
        }
        __syncthreads();
        // queries with c in [k0+1, k0+128]
        {
            int bu = ch + 1;
            int d = tid & 63;
            for (int q = boff[bu] + (tid >> 6); q < boff[bu + 1]; q += 4) {
                int i = qord[q];
                int off = ci[i] - k0 - 1;
                float val = fmaf(esS[i], TotA[d] - locA[off * 64 + d],
                                 es01S[i] * locB[off * 64 + d]);
                g_hp[(size_t)(b * NN + i) * CC + hh * DD + d] = val;
            }
        }
        __syncthreads();
    }
}

// ---------------------------------------------------------------------------
// K5: out = h_prime @ out_W + out_b    [8192 x 512] @ [512 x 64]
// ---------------------------------------------------------------------------
__global__ __launch_bounds__(256) void k5_out(const float* __restrict__ oW,
                                              const float* __restrict__ ob,
                                              float* __restrict__ out) {
    __shared__ __align__(16) float As[64][68];
    __shared__ __align__(16) float Bs[64][68];
    int tid = threadIdx.x;
    int r0 = blockIdx.x * 64;
    int tx = tid & 15, ty = tid >> 4;
    float acc[4][4] = {};
    for (int kt = 0; kt < CC; kt += 64) {
        __syncthreads();
        for (int idx = tid; idx < 4096; idx += 256) {
            int r = idx >> 6, k = idx & 63;
            As[r][k] = g_hp[(size_t)(r0 + r) * CC + kt + k];
            Bs[r][k] = oW[(size_t)(kt + r) * DD + k];
        }
        __syncthreads();
#pragma unroll
        for (int k4 = 0; k4 < 16; k4++) {
            float4 a4[4], b4[4];
#pragma unroll
            for (int r = 0; r < 4; r++) a4[r] = *(const float4*)&As[ty*4+r][k4*4];
#pragma unroll
            for (int kk = 0; kk < 4; kk++) b4[kk] = *(const float4*)&Bs[k4*4+kk][tx*4];
#pragma unroll
            for (int kk = 0; kk < 4; kk++) {
                float ak[4] = { kk==0?a4[0].x:kk==1?a4[0].y:kk==2?a4[0].z:a4[0].w,
                                kk==0?a4[1].x:kk==1?a4[1].y:kk==2?a4[1].z:a4[1].w,
                                kk==0?a4[2].x:kk==1?a4[2].y:kk==2?a4[2].z:a4[2].w,
                                kk==0?a4[3].x:kk==1?a4[3].y:kk==2?a4[3].z:a4[3].w };
                float bk[4] = { b4[kk].x, b4[kk].y, b4[kk].z, b4[kk].w };
#pragma unroll
                for (int r = 0; r < 4; r++)
#pragma unroll
                    for (int c = 0; c < 4; c++)
                        acc[r][c] = fmaf(ak[r], bk[c], acc[r][c]);
            }
        }
    }
#pragma unroll
    for (int r = 0; r < 4; r++)
#pragma unroll
        for (int c = 0; c < 4; c++)
            out[(size_t)(r0 + ty*4 + r) * DD + tx*4 + c] = acc[r][c] + ob[tx*4+c];
}

// ---------------------------------------------------------------------------
extern "C" void kernel_launch(void* const* d_in, const int* in_sizes, int n_in,
                              void* d_out, int out_size) {
    const float* h    = (const float*)d_in[0];
    const float* W    = (const float*)d_in[2];
    const float* a    = (const float*)d_in[3];
    const float* oW   = (const float*)d_in[4];
    const float* ob   = (const float*)d_in[5];
    float* out = (float*)d_out;

    cudaFuncSetAttribute(kF_attn, cudaFuncAttributeMaxDynamicSharedMemorySize,
                         KF_SMEM_BYTES);

    k0_wa <<<2, 256>>>(W, a);
    k1_wh <<<dim3(CC/64, (BB*NN)/64), 256>>>(h, W);
    k2_vec<<<(BB*NN)/32, 256>>>(h);
    kF_attn<<<BB*HH, 256, KF_SMEM_BYTES>>>();
    k5_out<<<(BB*NN)/64, 256>>>(oW, ob, out);
}